// round 1
// baseline (speedup 1.0000x reference)
#include <cuda_runtime.h>
#include <math.h>

// ---------------------------------------------------------------------------
// QuantumHybridCNN: conv1(1->32,k3,pad1)+relu+pool2 -> conv2(32->64,k3,pad1)
// +relu+pool2 -> fc(1024->64)+relu -> pre(64->4)+tanh*pi/2 -> 4-qubit circuit
// -> post(4->1)+sigmoid.   B = 32768, out (B,1) fp32.
// ---------------------------------------------------------------------------

#define BMAX 32768

// Intermediates as device globals (no allocation allowed).
// h1: [b][c=32][p=32]   h2: [b][flat=1024] where flat = o*16 + j
__device__ float g_h1[BMAX * 1024];
__device__ float g_h2[BMAX * 1024];

// ---------------------------------------------------------------------------
// Kernel 1: conv1 + relu + maxpool2.  8 samples per block, 256 threads.
// warp = one sample, lane = output channel. All smem reads broadcast.
// ---------------------------------------------------------------------------
__global__ void k_conv1(const float* __restrict__ x,
                        const float* __restrict__ w,
                        const float* __restrict__ bias,
                        float* __restrict__ h1, int B)
{
    __shared__ float xs[8][64];
    int tid = threadIdx.x;
    int b0 = blockIdx.x * 8;

    #pragma unroll
    for (int i = tid; i < 8 * 64; i += 256)
        xs[i >> 6][i & 63] = x[b0 * 64 + i];
    __syncthreads();

    int bl = tid >> 5;       // sample within block (0..7)
    int c  = tid & 31;       // output channel (0..31)
    int b  = b0 + bl;
    if (b >= B) return;

    float w0 = w[c * 3 + 0], w1 = w[c * 3 + 1], w2 = w[c * 3 + 2];
    float bb = bias[c];
    const float* xr = xs[bl];

    float out[32];
    #pragma unroll
    for (int j = 0; j < 32; j++) {
        int p = 2 * j;
        float xm = (p == 0) ? 0.0f : xr[p - 1];
        float xp = (p + 2 == 64) ? 0.0f : xr[p + 2];
        float y0 = fmaf(w0, xm,    fmaf(w1, xr[p],     fmaf(w2, xr[p + 1], bb)));
        float y1 = fmaf(w0, xr[p], fmaf(w1, xr[p + 1], fmaf(w2, xp,        bb)));
        out[j] = fmaxf(fmaxf(y0, 0.0f), fmaxf(y1, 0.0f));
    }

    float4* dst = (float4*)&h1[(b * 32 + c) * 32];
    #pragma unroll
    for (int j = 0; j < 8; j++) dst[j] = ((float4*)out)[j];
}

// ---------------------------------------------------------------------------
// Kernel 2: conv2 + relu + maxpool2.  4 samples per block, 256 threads.
// thread = (sample, out-channel). 32 register accumulators per thread.
// weights (24KB) + 4 h1 tiles (16KB) staged in smem; all h1 reads broadcast.
// ---------------------------------------------------------------------------
__global__ void k_conv2(const float* __restrict__ h1,
                        const float* __restrict__ w,
                        const float* __restrict__ bias,
                        float* __restrict__ h2, int B)
{
    __shared__ float ws[64 * 32 * 3];
    __shared__ float bs[64];
    __shared__ float hs[4][1024];

    int tid = threadIdx.x;
    int b0 = blockIdx.x * 4;

    for (int i = tid; i < 6144; i += 256) ws[i] = w[i];
    if (tid < 64) bs[tid] = bias[tid];
    for (int i = tid; i < 4096; i += 256)
        hs[i >> 10][i & 1023] = h1[b0 * 1024 + i];
    __syncthreads();

    int s = tid >> 6;    // sample within block (0..3)
    int o = tid & 63;    // output channel
    int b = b0 + s;
    if (b >= B) return;

    float acc[32];
    float bb = bs[o];
    #pragma unroll
    for (int p = 0; p < 32; p++) acc[p] = bb;

    const float* hrow = hs[s];
    const float* wrow = &ws[o * 96];

    for (int i = 0; i < 32; i++) {
        float w0 = wrow[i * 3 + 0], w1 = wrow[i * 3 + 1], w2 = wrow[i * 3 + 2];
        float r[32];
        const float4* rp = (const float4*)&hrow[i * 32];
        #pragma unroll
        for (int q = 0; q < 8; q++) ((float4*)r)[q] = rp[q];

        acc[0] = fmaf(w1, r[0], fmaf(w2, r[1], acc[0]));
        #pragma unroll
        for (int p = 1; p < 31; p++)
            acc[p] = fmaf(w0, r[p - 1], fmaf(w1, r[p], fmaf(w2, r[p + 1], acc[p])));
        acc[31] = fmaf(w0, r[30], fmaf(w1, r[31], acc[31]));
    }

    float out[16];
    #pragma unroll
    for (int j = 0; j < 16; j++)
        out[j] = fmaxf(fmaxf(acc[2 * j], acc[2 * j + 1]), 0.0f);

    float4* dst = (float4*)&h2[b * 1024 + o * 16];
    #pragma unroll
    for (int j = 0; j < 4; j++) dst[j] = ((float4*)out)[j];
}

// ---------------------------------------------------------------------------
// Quantum helpers: 16-amplitude real statevector in registers.
// Wire w -> bit mask: w0->8, w1->4, w2->2, w3->1.
// ---------------------------------------------------------------------------
__device__ __forceinline__ void apply_ry(float st[16], float th, int mask)
{
    float s, c;
    sincosf(th * 0.5f, &s, &c);
    #pragma unroll
    for (int i = 0; i < 16; i++) {
        if (!(i & mask)) {
            int j = i | mask;
            float a = st[i], b = st[j];
            st[i] = c * a - s * b;
            st[j] = s * a + c * b;
        }
    }
}

__device__ __forceinline__ void apply_cnot(float st[16], int cm, int tm)
{
    #pragma unroll
    for (int i = 0; i < 16; i++) {
        if ((i & cm) && !(i & tm)) {
            int j = i | tm;
            float t = st[i]; st[i] = st[j]; st[j] = t;
        }
    }
}

// ---------------------------------------------------------------------------
// Kernel 3: fc GEMM (64 samples x 64 outputs, K=1024) + relu, then per-sample
// pre->tanh->quantum->post->sigmoid tail. 256 threads: 16x16, 4x4 per thread.
// ---------------------------------------------------------------------------
__global__ void k_fc_tail(const float* __restrict__ h2,
                          const float* __restrict__ fcw,
                          const float* __restrict__ fcb,
                          const float* __restrict__ prew,
                          const float* __restrict__ preb,
                          const float* __restrict__ qp,
                          const float* __restrict__ postw,
                          const float* __restrict__ postb,
                          float* __restrict__ out, int B)
{
    __shared__ float As[64][20];   // 64 rows x 16 k (padded stride 20)
    __shared__ float Bs[16][64];
    __shared__ float Hs[64][65];   // relu(fc) outputs, padded to kill conflicts
    __shared__ float s_prew[256];
    __shared__ float s_preb[4], s_postw[4], s_postb[1];
    __shared__ float s_qp[24];

    int tid = threadIdx.x;
    int b0 = blockIdx.x * 64;

    if (tid < 256) s_prew[tid] = prew[tid];
    if (tid < 24)  s_qp[tid]   = qp[tid];
    if (tid < 4) { s_preb[tid] = preb[tid]; s_postw[tid] = postw[tid]; }
    if (tid == 0)  s_postb[0]  = postb[0];

    int tx = tid & 15, ty = tid >> 4;
    float acc[4][4] = {};

    int a_row = tid >> 2;
    int a_k4  = (tid & 3) * 4;
    int b_k   = tid >> 4;
    int b_c4  = (tid & 15) * 4;

    for (int kt = 0; kt < 1024; kt += 16) {
        float4 va = *(const float4*)&h2[(b0 + a_row) * 1024 + kt + a_k4];
        As[a_row][a_k4 + 0] = va.x; As[a_row][a_k4 + 1] = va.y;
        As[a_row][a_k4 + 2] = va.z; As[a_row][a_k4 + 3] = va.w;
        *(float4*)&Bs[b_k][b_c4] = *(const float4*)&fcw[(kt + b_k) * 64 + b_c4];
        __syncthreads();

        #pragma unroll
        for (int k = 0; k < 16; k++) {
            float a[4], bv[4];
            #pragma unroll
            for (int i = 0; i < 4; i++) a[i] = As[ty * 4 + i][k];
            #pragma unroll
            for (int j = 0; j < 4; j++) bv[j] = Bs[k][tx * 4 + j];
            #pragma unroll
            for (int i = 0; i < 4; i++)
                #pragma unroll
                for (int j = 0; j < 4; j++)
                    acc[i][j] = fmaf(a[i], bv[j], acc[i][j]);
        }
        __syncthreads();
    }

    // bias + relu into Hs
    #pragma unroll
    for (int i = 0; i < 4; i++)
        #pragma unroll
        for (int j = 0; j < 4; j++) {
            int c = tx * 4 + j;
            Hs[ty * 4 + i][c] = fmaxf(acc[i][j] + fcb[c], 0.0f);
        }
    __syncthreads();

    // Per-sample tail: threads 0..63 each handle one sample.
    if (tid < 64 && b0 + tid < B) {
        const float* h = Hs[tid];

        // pre: 64 -> 4, tanh * pi/2
        float qin[4];
        #pragma unroll
        for (int wq = 0; wq < 4; wq++) {
            float d = s_preb[wq];
            #pragma unroll 8
            for (int j = 0; j < 64; j++) d = fmaf(h[j], s_prew[j * 4 + wq], d);
            qin[wq] = tanhf(d) * 1.5707963267948966f;
        }

        // 4-qubit circuit
        float st[16];
        #pragma unroll
        for (int i = 0; i < 16; i++) st[i] = 0.25f;
        apply_ry(st, qin[0], 8);
        apply_ry(st, qin[1], 4);
        apply_ry(st, qin[2], 2);
        apply_ry(st, qin[3], 1);
        for (int k = 0; k < 6; k++) {
            apply_cnot(st, 8, 4);   // CNOT(0,1)
            apply_cnot(st, 2, 1);   // CNOT(2,3)
            apply_cnot(st, 4, 2);   // CNOT(1,2)
            apply_ry(st, s_qp[4 * k + 0], 8);
            apply_ry(st, s_qp[4 * k + 1], 4);
            apply_ry(st, s_qp[4 * k + 2], 2);
            apply_ry(st, s_qp[4 * k + 3], 1);
        }

        // Z expectations
        float z0 = 0.f, z1 = 0.f, z2 = 0.f, z3 = 0.f;
        #pragma unroll
        for (int i = 0; i < 16; i++) {
            float p = st[i] * st[i];
            z0 += (i & 8) ? -p : p;
            z1 += (i & 4) ? -p : p;
            z2 += (i & 2) ? -p : p;
            z3 += (i & 1) ? -p : p;
        }

        float t = s_postb[0];
        t = fmaf(z0, s_postw[0], t);
        t = fmaf(z1, s_postw[1], t);
        t = fmaf(z2, s_postw[2], t);
        t = fmaf(z3, s_postw[3], t);
        out[b0 + tid] = 1.0f / (1.0f + expf(-t));
    }
}

// ---------------------------------------------------------------------------
extern "C" void kernel_launch(void* const* d_in, const int* in_sizes, int n_in,
                              void* d_out, int out_size)
{
    const float* x       = (const float*)d_in[0];
    const float* conv1_w = (const float*)d_in[1];
    const float* conv1_b = (const float*)d_in[2];
    const float* conv2_w = (const float*)d_in[3];
    const float* conv2_b = (const float*)d_in[4];
    const float* fc_w    = (const float*)d_in[5];
    const float* fc_b    = (const float*)d_in[6];
    const float* pre_w   = (const float*)d_in[7];
    const float* pre_b   = (const float*)d_in[8];
    const float* q_par   = (const float*)d_in[9];
    const float* post_w  = (const float*)d_in[10];
    const float* post_b  = (const float*)d_in[11];
    float* out = (float*)d_out;

    int B = in_sizes[0] / 64;
    if (B > BMAX) B = BMAX;

    float* h1;
    float* h2;
    cudaGetSymbolAddress((void**)&h1, g_h1);
    cudaGetSymbolAddress((void**)&h2, g_h2);

    k_conv1<<<(B + 7) / 8, 256>>>(x, conv1_w, conv1_b, h1, B);
    k_conv2<<<(B + 3) / 4, 256>>>(h1, conv2_w, conv2_b, h2, B);
    k_fc_tail<<<(B + 63) / 64, 256>>>(h2, fc_w, fc_b, pre_w, pre_b, q_par,
                                      post_w, post_b, out, B);
}

// round 2
// speedup vs baseline: 2.0388x; 2.0388x over previous
#include <cuda_runtime.h>
#include <math.h>

// ---------------------------------------------------------------------------
// QuantumHybridCNN, f32x2-packed version.
//   Kernel A: conv1(1->32,k3)+relu+pool + conv2(32->64,k3)+relu+pool, fused.
//             8 samples/block; conv2 threads each compute ONE output channel
//             for TWO samples using packed fma.rn.f32x2.
//   Kernel B: fc(1024->64)+relu GEMM (128 samples x 64, f32x2 over row pairs)
//             + pre->tanh->4-qubit circuit->post->sigmoid tail.
// Intermediate h2 stored sample-pair-interleaved: h2p[pair][k*2 + (b&1)].
// ---------------------------------------------------------------------------

#define BMAX 32768
typedef unsigned long long u64;

__device__ float g_h2p[(BMAX / 2) * 2048];   // [B/2][1024][2]

// ---- f32x2 helpers --------------------------------------------------------
__device__ __forceinline__ u64 pack2(float lo, float hi) {
    u64 r; asm("mov.b64 %0, {%1,%2};" : "=l"(r) : "f"(lo), "f"(hi)); return r;
}
__device__ __forceinline__ u64 pack2s(float v) { return pack2(v, v); }
__device__ __forceinline__ u64 fma2(u64 a, u64 b, u64 c) {
    u64 d; asm("fma.rn.f32x2 %0, %1, %2, %3;" : "=l"(d) : "l"(a), "l"(b), "l"(c));
    return d;
}
__device__ __forceinline__ float2 unpack2(u64 v) {
    float lo, hi; asm("mov.b64 {%0,%1}, %2;" : "=f"(lo), "=f"(hi) : "l"(v));
    return make_float2(lo, hi);
}

// ---------------------------------------------------------------------------
// Kernel A: fused conv1 + conv2. 8 samples per block, 256 threads.
// ---------------------------------------------------------------------------
__global__ __launch_bounds__(256) void k_conv_fused(
    const float* __restrict__ x,
    const float* __restrict__ c1w, const float* __restrict__ c1b,
    const float* __restrict__ c2w, const float* __restrict__ c2b,
    float* __restrict__ h2p, int B)
{
    __shared__ float  xs[8][64];        // raw input
    __shared__ float2 hs2[4][1056];     // conv1 out, [pair][c*33+pos], (even,odd)
    __shared__ float  wst[96 * 64];     // conv2 w transposed: [(i*3+t)*64 + o]
    __shared__ float  bs[64];

    int tid = threadIdx.x;
    int b0  = blockIdx.x * 8;

    // ---- stage input + conv2 weights (transposed) ----
    #pragma unroll
    for (int i = tid; i < 512; i += 256) xs[i >> 6][i & 63] = x[b0 * 64 + i];
    for (int idx = tid; idx < 6144; idx += 256) {
        int o = idx / 96, r = idx % 96;          // r = i*3 + t
        wst[r * 64 + o] = c2w[idx];
    }
    if (tid < 64) bs[tid] = c2b[tid];
    __syncthreads();

    // ---- conv1 + relu + pool: thread = (sample s, channel c) ----
    {
        int s = tid >> 5, c = tid & 31;
        float w0 = __ldg(&c1w[c * 3 + 0]);
        float w1 = __ldg(&c1w[c * 3 + 1]);
        float w2 = __ldg(&c1w[c * 3 + 2]);
        float bb = __ldg(&c1b[c]);
        const float* xr = xs[s];
        float* dst = ((float*)&hs2[s >> 1][c * 33]) + (s & 1);
        #pragma unroll
        for (int j = 0; j < 32; j++) {
            int p = 2 * j;
            float xm = (p == 0)      ? 0.0f : xr[p - 1];
            float xp = (p + 2 == 64) ? 0.0f : xr[p + 2];
            float y0 = fmaf(w0, xm,    fmaf(w1, xr[p],     fmaf(w2, xr[p + 1], bb)));
            float y1 = fmaf(w0, xr[p], fmaf(w1, xr[p + 1], fmaf(w2, xp,        bb)));
            dst[2 * j] = fmaxf(fmaxf(y0, 0.0f), fmaxf(y1, 0.0f));
        }
    }
    __syncthreads();

    // ---- conv2: thread = (sample-pair, out channel o), f32x2 packed ----
    int pair = tid >> 6;    // 0..3
    int o    = tid & 63;

    u64 acc[32];
    {
        u64 bb2 = pack2s(bs[o]);
        #pragma unroll
        for (int p = 0; p < 32; p++) acc[p] = bb2;
    }

    const float2* hrow = hs2[pair];
    for (int i = 0; i < 32; i++) {
        float w0 = wst[(i * 3 + 0) * 64 + o];
        float w1 = wst[(i * 3 + 1) * 64 + o];
        float w2 = wst[(i * 3 + 2) * 64 + o];
        u64 w0p = pack2s(w0), w1p = pack2s(w1), w2p = pack2s(w2);

        const u64* rr = (const u64*)&hrow[i * 33];
        u64 rm = 0ULL;            // zero-pad left
        u64 r0 = rr[0];
        #pragma unroll
        for (int p = 0; p < 32; p++) {
            u64 rp1 = (p < 31) ? rr[p + 1] : 0ULL;   // zero-pad right
            acc[p] = fma2(w0p, rm, fma2(w1p, r0, fma2(w2p, rp1, acc[p])));
            rm = r0; r0 = rp1;
        }
    }

    // ---- relu + pool2, write pair-interleaved h2p ----
    float* dst = &h2p[(size_t)(blockIdx.x * 4 + pair) * 2048 + o * 32];
    #pragma unroll
    for (int j = 0; j < 16; j++) {
        float2 a = unpack2(acc[2 * j]);
        float2 b = unpack2(acc[2 * j + 1]);
        float2 r;
        r.x = fmaxf(fmaxf(a.x, b.x), 0.0f);
        r.y = fmaxf(fmaxf(a.y, b.y), 0.0f);
        ((float2*)dst)[j] = r;
    }
}

// ---------------------------------------------------------------------------
// Quantum helpers: 16-amplitude real statevector in registers.
// Wire w -> bit mask: w0->8, w1->4, w2->2, w3->1.
// ---------------------------------------------------------------------------
__device__ __forceinline__ void apply_ry(float st[16], float th, int mask)
{
    float s, c;
    sincosf(th * 0.5f, &s, &c);
    #pragma unroll
    for (int i = 0; i < 16; i++) {
        if (!(i & mask)) {
            int j = i | mask;
            float a = st[i], b = st[j];
            st[i] = c * a - s * b;
            st[j] = s * a + c * b;
        }
    }
}

__device__ __forceinline__ void apply_cnot(float st[16], int cm, int tm)
{
    #pragma unroll
    for (int i = 0; i < 16; i++) {
        if ((i & cm) && !(i & tm)) {
            int j = i | tm;
            float t = st[i]; st[i] = st[j]; st[j] = t;
        }
    }
}

// ---------------------------------------------------------------------------
// Kernel B: fc GEMM (128 samples x 64 cols, K=1024) + relu + quantum tail.
// 256 threads = 16 (ty: row-pair groups) x 16 (tx: col groups of 4).
// Thread computes 4 row-pairs x 4 cols with f32x2 (8 rows x 4 cols).
// ---------------------------------------------------------------------------
__global__ __launch_bounds__(256) void k_fc_tail(
    const float* __restrict__ h2p,
    const float* __restrict__ fcw, const float* __restrict__ fcb,
    const float* __restrict__ prew, const float* __restrict__ preb,
    const float* __restrict__ qp,
    const float* __restrict__ postw, const float* __restrict__ postb,
    float* __restrict__ out, int B)
{
    __shared__ float As2[64 * 34];     // [rp][k*2+comp], stride 34
    __shared__ float Bs[16 * 64];      // [k][c]
    __shared__ float Hs[128 * 65];     // relu(fc) rows, stride 65
    __shared__ float s_prew[256];
    __shared__ float s_fcb[64];
    __shared__ float s_preb[4], s_postw[4], s_postb[1];
    __shared__ float s_qp[24];

    int tid = threadIdx.x;
    int b0  = blockIdx.x * 128;

    s_prew[tid] = prew[tid];
    if (tid < 64) s_fcb[tid] = fcb[tid];
    if (tid < 24) s_qp[tid] = qp[tid];
    if (tid < 4) { s_preb[tid] = preb[tid]; s_postw[tid] = postw[tid]; }
    if (tid == 0) s_postb[0] = postb[0];

    int tx = tid & 15, ty = tid >> 4;
    u64 acc[4][4];
    #pragma unroll
    for (int i = 0; i < 4; i++)
        #pragma unroll
        for (int c = 0; c < 4; c++) acc[i][c] = 0ULL;

    // staging indices
    int a_rp    = tid >> 2;            // 0..63 (row pair)
    int a_chunk = (tid & 3) * 8;       // float offset within 32-float row
    int bk      = tid >> 4;            // 0..15
    int bc      = (tid & 15) * 4;

    const float* a_src = &h2p[(size_t)(blockIdx.x * 64 + a_rp) * 2048 + a_chunk];

    for (int kt = 0; kt < 1024; kt += 16) {
        // stage A (pair-interleaved rows) and B
        float4 v0 = *(const float4*)(a_src + kt * 2);
        float4 v1 = *(const float4*)(a_src + kt * 2 + 4);
        float* ad = &As2[a_rp * 34 + a_chunk];
        ((float2*)ad)[0] = make_float2(v0.x, v0.y);
        ((float2*)ad)[1] = make_float2(v0.z, v0.w);
        ((float2*)ad)[2] = make_float2(v1.x, v1.y);
        ((float2*)ad)[3] = make_float2(v1.z, v1.w);
        *(float4*)&Bs[bk * 64 + bc] = *(const float4*)&fcw[(kt + bk) * 64 + bc];
        __syncthreads();

        #pragma unroll
        for (int k = 0; k < 16; k++) {
            float4 w = *(const float4*)&Bs[k * 64 + tx * 4];
            u64 bp0 = pack2s(w.x), bp1 = pack2s(w.y);
            u64 bp2 = pack2s(w.z), bp3 = pack2s(w.w);
            u64 a0 = *(const u64*)&As2[(ty * 4 + 0) * 34 + 2 * k];
            u64 a1 = *(const u64*)&As2[(ty * 4 + 1) * 34 + 2 * k];
            u64 a2 = *(const u64*)&As2[(ty * 4 + 2) * 34 + 2 * k];
            u64 a3 = *(const u64*)&As2[(ty * 4 + 3) * 34 + 2 * k];
            acc[0][0] = fma2(a0, bp0, acc[0][0]);
            acc[0][1] = fma2(a0, bp1, acc[0][1]);
            acc[0][2] = fma2(a0, bp2, acc[0][2]);
            acc[0][3] = fma2(a0, bp3, acc[0][3]);
            acc[1][0] = fma2(a1, bp0, acc[1][0]);
            acc[1][1] = fma2(a1, bp1, acc[1][1]);
            acc[1][2] = fma2(a1, bp2, acc[1][2]);
            acc[1][3] = fma2(a1, bp3, acc[1][3]);
            acc[2][0] = fma2(a2, bp0, acc[2][0]);
            acc[2][1] = fma2(a2, bp1, acc[2][1]);
            acc[2][2] = fma2(a2, bp2, acc[2][2]);
            acc[2][3] = fma2(a2, bp3, acc[2][3]);
            acc[3][0] = fma2(a3, bp0, acc[3][0]);
            acc[3][1] = fma2(a3, bp1, acc[3][1]);
            acc[3][2] = fma2(a3, bp2, acc[3][2]);
            acc[3][3] = fma2(a3, bp3, acc[3][3]);
        }
        __syncthreads();
    }

    // bias + relu -> Hs (de-interleave row pairs)
    #pragma unroll
    for (int i = 0; i < 4; i++) {
        int rp = ty * 4 + i;
        #pragma unroll
        for (int c = 0; c < 4; c++) {
            int col = tx * 4 + c;
            float bb = s_fcb[col];
            float2 v = unpack2(acc[i][c]);
            Hs[(rp * 2 + 0) * 65 + col] = fmaxf(v.x + bb, 0.0f);
            Hs[(rp * 2 + 1) * 65 + col] = fmaxf(v.y + bb, 0.0f);
        }
    }
    __syncthreads();

    // ---- per-sample tail: threads 0..127 ----
    if (tid < 128 && b0 + tid < B) {
        const float* h = &Hs[tid * 65];

        float qin[4];
        #pragma unroll
        for (int wq = 0; wq < 4; wq++) {
            float d = s_preb[wq];
            #pragma unroll 8
            for (int j = 0; j < 64; j++) d = fmaf(h[j], s_prew[j * 4 + wq], d);
            qin[wq] = tanhf(d) * 1.5707963267948966f;
        }

        float st[16];
        #pragma unroll
        for (int i = 0; i < 16; i++) st[i] = 0.25f;
        apply_ry(st, qin[0], 8);
        apply_ry(st, qin[1], 4);
        apply_ry(st, qin[2], 2);
        apply_ry(st, qin[3], 1);
        for (int k = 0; k < 6; k++) {
            apply_cnot(st, 8, 4);   // CNOT(0,1)
            apply_cnot(st, 2, 1);   // CNOT(2,3)
            apply_cnot(st, 4, 2);   // CNOT(1,2)
            apply_ry(st, s_qp[4 * k + 0], 8);
            apply_ry(st, s_qp[4 * k + 1], 4);
            apply_ry(st, s_qp[4 * k + 2], 2);
            apply_ry(st, s_qp[4 * k + 3], 1);
        }

        float z0 = 0.f, z1 = 0.f, z2 = 0.f, z3 = 0.f;
        #pragma unroll
        for (int i = 0; i < 16; i++) {
            float p = st[i] * st[i];
            z0 += (i & 8) ? -p : p;
            z1 += (i & 4) ? -p : p;
            z2 += (i & 2) ? -p : p;
            z3 += (i & 1) ? -p : p;
        }

        float t = s_postb[0];
        t = fmaf(z0, s_postw[0], t);
        t = fmaf(z1, s_postw[1], t);
        t = fmaf(z2, s_postw[2], t);
        t = fmaf(z3, s_postw[3], t);
        out[b0 + tid] = 1.0f / (1.0f + expf(-t));
    }
}

// ---------------------------------------------------------------------------
extern "C" void kernel_launch(void* const* d_in, const int* in_sizes, int n_in,
                              void* d_out, int out_size)
{
    const float* x       = (const float*)d_in[0];
    const float* conv1_w = (const float*)d_in[1];
    const float* conv1_b = (const float*)d_in[2];
    const float* conv2_w = (const float*)d_in[3];
    const float* conv2_b = (const float*)d_in[4];
    const float* fc_w    = (const float*)d_in[5];
    const float* fc_b    = (const float*)d_in[6];
    const float* pre_w   = (const float*)d_in[7];
    const float* pre_b   = (const float*)d_in[8];
    const float* q_par   = (const float*)d_in[9];
    const float* post_w  = (const float*)d_in[10];
    const float* post_b  = (const float*)d_in[11];
    float* out = (float*)d_out;

    int B = in_sizes[0] / 64;
    if (B > BMAX) B = BMAX;

    float* h2p;
    cudaGetSymbolAddress((void**)&h2p, g_h2p);

    k_conv_fused<<<(B + 7) / 8, 256>>>(x, conv1_w, conv1_b, conv2_w, conv2_b,
                                       h2p, B);
    k_fc_tail<<<(B + 127) / 128, 256>>>(h2p, fc_w, fc_b, pre_w, pre_b, q_par,
                                        post_w, post_b, out, B);
}

// round 3
// speedup vs baseline: 3.9887x; 1.9564x over previous
#include <cuda_runtime.h>
#include <math.h>
#include <stdint.h>

// ---------------------------------------------------------------------------
// QuantumHybridCNN, tf32 tensor-core version.
//  k_conv:   conv1 (fp32 scalar) fused with conv2 as implicit GEMM via
//            mma.sync.m16n8k8.tf32. 8 samples/block, warp = sample.
//            M=32 positions, N=64 ch, K=96 (k = t*32 + c).
//  k_fc_tail: fc GEMM (128 samples x 64, K=1024) via tf32 MMA + quantum tail.
//  h2 stored position-major: h2[b][j*64 + o]; fc stage permutes fcw rows.
// ---------------------------------------------------------------------------

#define BMAX 32768
__device__ float g_h2[(size_t)BMAX * 1024];

__device__ __forceinline__ float to_tf32(float v) {
    float r; asm("cvt.rna.tf32.f32 %0, %1;" : "=f"(r) : "f"(v)); return r;
}
__device__ __forceinline__ uint32_t fbits(float v) { return __float_as_uint(v); }

__device__ __forceinline__ void mma8(float d[4], const uint32_t a[4],
                                     uint32_t b0, uint32_t b1) {
    asm volatile(
        "mma.sync.aligned.m16n8k8.row.col.f32.tf32.tf32.f32 "
        "{%0,%1,%2,%3}, {%4,%5,%6,%7}, {%8,%9}, {%0,%1,%2,%3};"
        : "+f"(d[0]), "+f"(d[1]), "+f"(d[2]), "+f"(d[3])
        : "r"(a[0]), "r"(a[1]), "r"(a[2]), "r"(a[3]), "r"(b0), "r"(b1));
}

// ---------------------------------------------------------------------------
// Kernel 1: conv1 (scalar fp32) + conv2 (tf32 MMA implicit GEMM).
// smem floats: xs 512 | hs 8*32*40 | wsB 96*72 | bs 64
// ---------------------------------------------------------------------------
#define CONV_SMEM_FLOATS (512 + 8 * 32 * 40 + 96 * 72 + 64)

__global__ __launch_bounds__(256) void k_conv(
    const float* __restrict__ x,
    const float* __restrict__ c1w, const float* __restrict__ c1b,
    const float* __restrict__ c2w, const float* __restrict__ c2b,
    float* __restrict__ h2, int B)
{
    extern __shared__ float sm[];
    float* xs  = sm;             // [8][64]
    float* hs  = sm + 512;       // [8][32][40]  padded conv1 out (idx = pos+1)
    float* wsB = hs + 10240;     // [96][72]     tf32 weights, k = t*32+c
    float* bs  = wsB + 6912;     // [64]

    int tid = threadIdx.x;
    int b0  = blockIdx.x * 8;

    for (int i = tid; i < 512; i += 256) xs[i] = x[b0 * 64 + i];
    for (int i = tid; i < 6144; i += 256) {
        int k = i >> 6, o = i & 63;
        int t = k >> 5, c = k & 31;
        wsB[k * 72 + o] = to_tf32(c2w[o * 96 + c * 3 + t]);
    }
    if (tid < 64) bs[tid] = c2b[tid];
    __syncthreads();

    // ---- conv1 + relu + pool (fp32), rounded to tf32 into hs ----
    {
        int s = tid >> 5, c = tid & 31;
        float w0 = __ldg(&c1w[c * 3 + 0]);
        float w1 = __ldg(&c1w[c * 3 + 1]);
        float w2 = __ldg(&c1w[c * 3 + 2]);
        float bb = __ldg(&c1b[c]);
        const float* xr = &xs[s * 64];
        float* hrow = &hs[(s * 32 + c) * 40];
        hrow[0] = 0.0f; hrow[33] = 0.0f;
        #pragma unroll
        for (int j = 0; j < 32; j++) {
            int p = 2 * j;
            float xm = (p == 0)  ? 0.0f : xr[p - 1];
            float xp = (p == 62) ? 0.0f : xr[p + 2];
            float y0 = fmaf(w0, xm,    fmaf(w1, xr[p],     fmaf(w2, xr[p + 1], bb)));
            float y1 = fmaf(w0, xr[p], fmaf(w1, xr[p + 1], fmaf(w2, xp,        bb)));
            hrow[j + 1] = to_tf32(fmaxf(fmaxf(y0, y1), 0.0f));
        }
    }
    __syncthreads();

    // ---- conv2 as tf32 MMA. warp = sample. M=32 (2 m16), N=64 (8 n8), K=96 ----
    int lane = tid & 31, s = tid >> 5;
    int gid = lane >> 2, tid4 = lane & 3;
    const float* hsS = &hs[s * 1280];

    float acc[2][8][4];
    #pragma unroll
    for (int mt = 0; mt < 2; mt++)
        #pragma unroll
        for (int nb = 0; nb < 8; nb++)
            #pragma unroll
            for (int q = 0; q < 4; q++) acc[mt][nb][q] = 0.0f;

    #pragma unroll
    for (int ks = 0; ks < 12; ks++) {
        int k0 = ks * 8;
        int t  = k0 >> 5;
        int c0 = (k0 & 31) + tid4;
        uint32_t a[2][4];
        #pragma unroll
        for (int mt = 0; mt < 2; mt++) {
            int p = mt * 16 + gid + t;   // A[p][k] = h1pad[c][p + t]
            a[mt][0] = fbits(hsS[c0 * 40 + p]);
            a[mt][1] = fbits(hsS[c0 * 40 + p + 8]);
            a[mt][2] = fbits(hsS[(c0 + 4) * 40 + p]);
            a[mt][3] = fbits(hsS[(c0 + 4) * 40 + p + 8]);
        }
        #pragma unroll
        for (int nb = 0; nb < 8; nb++) {
            uint32_t bb0 = fbits(wsB[(k0 + tid4) * 72 + nb * 8 + gid]);
            uint32_t bb1 = fbits(wsB[(k0 + tid4 + 4) * 72 + nb * 8 + gid]);
            mma8(acc[0][nb], a[0], bb0, bb1);
            mma8(acc[1][nb], a[1], bb0, bb1);
        }
    }

    // ---- bias + relu + pool (shfl pairs rows p, p+1) + store h2[j*64+o] ----
    float* dst = &h2[(size_t)(b0 + s) * 1024];
    #pragma unroll
    for (int mt = 0; mt < 2; mt++) {
        #pragma unroll
        for (int nb = 0; nb < 8; nb++) {
            int cb = nb * 8 + 2 * tid4;
            float bb0 = bs[cb], bb1 = bs[cb + 1];
            float v0 = fmaxf(acc[mt][nb][0] + bb0, 0.0f);
            float v1 = fmaxf(acc[mt][nb][1] + bb1, 0.0f);
            float v2 = fmaxf(acc[mt][nb][2] + bb0, 0.0f);
            float v3 = fmaxf(acc[mt][nb][3] + bb1, 0.0f);
            float q0 = __shfl_xor_sync(0xffffffffu, v0, 4);
            float q1 = __shfl_xor_sync(0xffffffffu, v1, 4);
            float q2 = __shfl_xor_sync(0xffffffffu, v2, 4);
            float q3 = __shfl_xor_sync(0xffffffffu, v3, 4);
            if (!(gid & 1)) {
                int j0 = mt * 8 + (gid >> 1);     // rows p, p+1
                int j1 = j0 + 4;                  // rows p+8, p+9
                *(float2*)&dst[j0 * 64 + cb] = make_float2(fmaxf(v0, q0), fmaxf(v1, q1));
                *(float2*)&dst[j1 * 64 + cb] = make_float2(fmaxf(v2, q2), fmaxf(v3, q3));
            }
        }
    }
}

// ---------------------------------------------------------------------------
// Quantum helpers (16 real amplitudes in registers).
// ---------------------------------------------------------------------------
__device__ __forceinline__ void apply_ry(float st[16], float th, int mask)
{
    float s, c;
    sincosf(th * 0.5f, &s, &c);
    #pragma unroll
    for (int i = 0; i < 16; i++) {
        if (!(i & mask)) {
            int j = i | mask;
            float a = st[i], b = st[j];
            st[i] = c * a - s * b;
            st[j] = s * a + c * b;
        }
    }
}
__device__ __forceinline__ void apply_cnot(float st[16], int cm, int tm)
{
    #pragma unroll
    for (int i = 0; i < 16; i++) {
        if ((i & cm) && !(i & tm)) {
            int j = i | tm;
            float t = st[i]; st[i] = st[j]; st[j] = t;
        }
    }
}

// ---------------------------------------------------------------------------
// Kernel 2: fc GEMM (tf32 MMA) + quantum tail. 128 samples/block, 256 thr.
// warps: wm (0..3) x wn (0..1): each warp m32 x n32, K chunks of 32.
// smem floats: As 128*36 | Bs 32*72 | Hs 128*65 | consts
// ---------------------------------------------------------------------------
#define FC_SMEM_FLOATS (128 * 36 + 32 * 72 + 128 * 65 + 256 + 64 + 24 + 12)

__global__ __launch_bounds__(256) void k_fc_tail(
    const float* __restrict__ h2, const float* __restrict__ fcw,
    const float* __restrict__ fcb, const float* __restrict__ prew,
    const float* __restrict__ preb, const float* __restrict__ qp,
    const float* __restrict__ postw, const float* __restrict__ postb,
    float* __restrict__ out, int B)
{
    extern __shared__ float sm[];
    float* As     = sm;            // [128][36]
    float* Bs     = sm + 4608;     // [32][72]
    float* Hs     = sm + 6912;     // [128][65]
    float* s_prew = sm + 15232;    // 256
    float* s_fcb  = sm + 15488;    // 64
    float* s_qp   = sm + 15552;    // 24
    float* s_misc = sm + 15576;    // preb[0..3], postw[4..7], postb[8]

    int tid = threadIdx.x;
    int b0  = blockIdx.x * 128;
    int lane = tid & 31, warp = tid >> 5;
    int gid = lane >> 2, tid4 = lane & 3;
    int wm = warp & 3, wn = warp >> 2;

    s_prew[tid] = prew[tid];
    if (tid < 64) s_fcb[tid] = fcb[tid];
    if (tid < 24) s_qp[tid] = qp[tid];
    if (tid < 4) { s_misc[tid] = preb[tid]; s_misc[4 + tid] = postw[tid]; }
    if (tid == 0) s_misc[8] = postb[0];

    float acc[2][4][4];
    #pragma unroll
    for (int mt = 0; mt < 2; mt++)
        #pragma unroll
        for (int nb = 0; nb < 4; nb++)
            #pragma unroll
            for (int q = 0; q < 4; q++) acc[mt][nb][q] = 0.0f;

    int a_r = tid >> 1, a_h = (tid & 1) * 16;
    const float* a_src = &h2[(size_t)(b0 + a_r) * 1024 + a_h];
    int b_kr = tid >> 3, b_c = (tid & 7) * 8;

    for (int chunk = 0; chunk < 32; chunk++) {
        int k0 = chunk * 32;
        {   // stage A (tf32-rounded)
            const float4* s4 = (const float4*)(a_src + k0);
            float* d = &As[a_r * 36 + a_h];
            #pragma unroll
            for (int q = 0; q < 4; q++) {
                float4 v = s4[q];
                d[q * 4 + 0] = to_tf32(v.x); d[q * 4 + 1] = to_tf32(v.y);
                d[q * 4 + 2] = to_tf32(v.z); d[q * 4 + 3] = to_tf32(v.w);
            }
        }
        {   // stage B: h2 k' = j*64+o  ->  fcw row (o*16 + j)
            int kp = k0 + b_kr;
            int orig = ((kp & 63) << 4) + (kp >> 6);
            const float4* s4 = (const float4*)&fcw[orig * 64 + b_c];
            float* d = &Bs[b_kr * 72 + b_c];
            #pragma unroll
            for (int q = 0; q < 2; q++) {
                float4 v = s4[q];
                d[q * 4 + 0] = to_tf32(v.x); d[q * 4 + 1] = to_tf32(v.y);
                d[q * 4 + 2] = to_tf32(v.z); d[q * 4 + 3] = to_tf32(v.w);
            }
        }
        __syncthreads();

        #pragma unroll
        for (int ks = 0; ks < 4; ks++) {
            int kk = ks * 8;
            uint32_t a[2][4];
            #pragma unroll
            for (int mt = 0; mt < 2; mt++) {
                int r = wm * 32 + mt * 16 + gid;
                a[mt][0] = fbits(As[r * 36 + kk + tid4]);
                a[mt][1] = fbits(As[(r + 8) * 36 + kk + tid4]);
                a[mt][2] = fbits(As[r * 36 + kk + tid4 + 4]);
                a[mt][3] = fbits(As[(r + 8) * 36 + kk + tid4 + 4]);
            }
            #pragma unroll
            for (int nb = 0; nb < 4; nb++) {
                uint32_t bb0 = fbits(Bs[(kk + tid4) * 72 + wn * 32 + nb * 8 + gid]);
                uint32_t bb1 = fbits(Bs[(kk + tid4 + 4) * 72 + wn * 32 + nb * 8 + gid]);
                mma8(acc[0][nb], a[0], bb0, bb1);
                mma8(acc[1][nb], a[1], bb0, bb1);
            }
        }
        __syncthreads();
    }

    // bias + relu -> Hs
    #pragma unroll
    for (int mt = 0; mt < 2; mt++) {
        #pragma unroll
        for (int nb = 0; nb < 4; nb++) {
            int r  = wm * 32 + mt * 16 + gid;
            int cb = wn * 32 + nb * 8 + 2 * tid4;
            float bb0 = s_fcb[cb], bb1 = s_fcb[cb + 1];
            Hs[r * 65 + cb]           = fmaxf(acc[mt][nb][0] + bb0, 0.0f);
            Hs[r * 65 + cb + 1]       = fmaxf(acc[mt][nb][1] + bb1, 0.0f);
            Hs[(r + 8) * 65 + cb]     = fmaxf(acc[mt][nb][2] + bb0, 0.0f);
            Hs[(r + 8) * 65 + cb + 1] = fmaxf(acc[mt][nb][3] + bb1, 0.0f);
        }
    }
    __syncthreads();

    // ---- per-sample tail ----
    if (tid < 128 && b0 + tid < B) {
        const float* h = &Hs[tid * 65];

        float qin[4];
        #pragma unroll
        for (int wq = 0; wq < 4; wq++) {
            float d = s_misc[wq];
            #pragma unroll 8
            for (int j = 0; j < 64; j++) d = fmaf(h[j], s_prew[j * 4 + wq], d);
            qin[wq] = tanhf(d) * 1.5707963267948966f;
        }

        float st[16];
        #pragma unroll
        for (int i = 0; i < 16; i++) st[i] = 0.25f;
        apply_ry(st, qin[0], 8);
        apply_ry(st, qin[1], 4);
        apply_ry(st, qin[2], 2);
        apply_ry(st, qin[3], 1);
        for (int k = 0; k < 6; k++) {
            apply_cnot(st, 8, 4);
            apply_cnot(st, 2, 1);
            apply_cnot(st, 4, 2);
            apply_ry(st, s_qp[4 * k + 0], 8);
            apply_ry(st, s_qp[4 * k + 1], 4);
            apply_ry(st, s_qp[4 * k + 2], 2);
            apply_ry(st, s_qp[4 * k + 3], 1);
        }

        float z0 = 0.f, z1 = 0.f, z2 = 0.f, z3 = 0.f;
        #pragma unroll
        for (int i = 0; i < 16; i++) {
            float p = st[i] * st[i];
            z0 += (i & 8) ? -p : p;
            z1 += (i & 4) ? -p : p;
            z2 += (i & 2) ? -p : p;
            z3 += (i & 1) ? -p : p;
        }

        float t = s_misc[8];
        t = fmaf(z0, s_misc[4], t);
        t = fmaf(z1, s_misc[5], t);
        t = fmaf(z2, s_misc[6], t);
        t = fmaf(z3, s_misc[7], t);
        out[b0 + tid] = 1.0f / (1.0f + expf(-t));
    }
}

// ---------------------------------------------------------------------------
extern "C" void kernel_launch(void* const* d_in, const int* in_sizes, int n_in,
                              void* d_out, int out_size)
{
    const float* x       = (const float*)d_in[0];
    const float* conv1_w = (const float*)d_in[1];
    const float* conv1_b = (const float*)d_in[2];
    const float* conv2_w = (const float*)d_in[3];
    const float* conv2_b = (const float*)d_in[4];
    const float* fc_w    = (const float*)d_in[5];
    const float* fc_b    = (const float*)d_in[6];
    const float* pre_w   = (const float*)d_in[7];
    const float* pre_b   = (const float*)d_in[8];
    const float* q_par   = (const float*)d_in[9];
    const float* post_w  = (const float*)d_in[10];
    const float* post_b  = (const float*)d_in[11];
    float* out = (float*)d_out;

    int B = in_sizes[0] / 64;
    if (B > BMAX) B = BMAX;

    float* h2;
    cudaGetSymbolAddress((void**)&h2, g_h2);

    size_t conv_sm = CONV_SMEM_FLOATS * sizeof(float);
    size_t fc_sm   = FC_SMEM_FLOATS * sizeof(float);
    cudaFuncSetAttribute(k_conv, cudaFuncAttributeMaxDynamicSharedMemorySize,
                         (int)conv_sm);
    cudaFuncSetAttribute(k_fc_tail, cudaFuncAttributeMaxDynamicSharedMemorySize,
                         (int)fc_sm);

    k_conv<<<(B + 7) / 8, 256, conv_sm>>>(x, conv1_w, conv1_b, conv2_w, conv2_b,
                                          h2, B);
    k_fc_tail<<<(B + 127) / 128, 256, fc_sm>>>(h2, fc_w, fc_b, pre_w, pre_b,
                                               q_par, post_w, post_b, out, B);
}